// round 15
// baseline (speedup 1.0000x reference)
#include <cuda_runtime.h>
#include <cuda_fp16.h>

// Round 15: in-kernel K1/K2 pipelining (streams failed twice: R12/R13 ran
// perfectly serial). Points processed in 4096-pt subtiles; the 8 pair-blocks
// of a chunk atomically count completions per subtile, and the 8TH ARRIVER
// transposes that subtile (scratch L2-hot) using 33KB staging smem beside the
// 128KB tables (164KB total, 1 CTA/SM). threadfence-reduction pattern;
// counters never reset: each launch adds exactly 8 per slot, so
// (old & 7) == 7 marks this launch's last arriver (graph-replay safe).

#define NLV 16
#define TBL 16384
#define BT  1024
#define NCHUNK 37          // grid (8,37) = 296 blocks = 2 waves
#define SUBT 4096          // pipeline granule
#define TPW 512            // transpose tile inside a subtile
#define TSTR 514           // staging stride (conflict-free)
#define SC   8192.0f
#define SCI  (1.0f / 8192.0f)
#define MAXB 1048576

__device__ __half2 g_scr[NLV * MAXB];     // 64 MB (level, point)
__device__ unsigned g_ctr[NCHUNK * 32];   // subtile arrival counters

__constant__ int c_res[NLV]  = {16, 20, 25, 32, 40, 50, 64, 80,
                                101, 128, 161, 203, 256, 322, 406, 512};
__constant__ int c_nenc[NLV] = {4096, 8000, 15625, 16384, 16384, 16384, 16384, 16384,
                                16384, 16384, 16384, 16384, 16384, 16384, 16384, 16384};

__device__ __forceinline__ float2 level_compute(
    float px, float py, float pz, int res, int nenc, bool hashing,
    const __half2* __restrict__ tab)
{
    const float resf = (float)res;
    const float sx = (px + 1.0f) * resf * 0.5f - 0.5f;
    const float sy = (py + 1.0f) * resf * 0.5f - 0.5f;
    const float sz = (pz + 1.0f) * resf * 0.5f - 0.5f;
    const float flx = floorf(sx), fly = floorf(sy), flz = floorf(sz);
    const float fx = sx - flx, fy = sy - fly, fz = sz - flz;
    const int cx = (int)flx, cy = (int)fly, cz = (int)flz;

    const float wx0 = (cx >= 0)       ? 1.0f - fx : 0.0f;
    const float wx1 = (cx <  res - 1) ? fx        : 0.0f;
    const float wy0 = (cy >= 0)       ? 1.0f - fy : 0.0f;
    const float wy1 = (cy <  res - 1) ? fy        : 0.0f;
    const float wz0 = (cz >= 0)       ? 1.0f - fz : 0.0f;
    const float wz1 = (cz <  res - 1) ? fz        : 0.0f;

    const float w00 = wx0 * wy0, w01 = wx0 * wy1;
    const float w10 = wx1 * wy0, w11 = wx1 * wy1;

    unsigned id[8];
    if (hashing) {
        const unsigned hx0 = (unsigned)cx;
        const unsigned hx1 = (unsigned)(cx + 1);
        const unsigned hy0 = (unsigned)cy       * 2654435761u;
        const unsigned hy1 = (unsigned)(cy + 1) * 2654435761u;
        const unsigned hz0 = (unsigned)cz       * 805459861u;
        const unsigned hz1 = (unsigned)(cz + 1) * 805459861u;
        const unsigned g00 = hx0 ^ hy0, g01 = hx0 ^ hy1;
        const unsigned g10 = hx1 ^ hy0, g11 = hx1 ^ hy1;
        const unsigned m = (unsigned)(nenc - 1);
        id[0] = (g00 ^ hz0) & m;  id[1] = (g00 ^ hz1) & m;
        id[2] = (g01 ^ hz0) & m;  id[3] = (g01 ^ hz1) & m;
        id[4] = (g10 ^ hz0) & m;  id[5] = (g10 ^ hz1) & m;
        id[6] = (g11 ^ hz0) & m;  id[7] = (g11 ^ hz1) & m;
    } else {
        const int r2 = res * res;
        const int a0 = cx,        a1 = cx + 1;
        const int b0v = cy * res, b1v = (cy + 1) * res;
        const int c0v = cz * r2,  c1v = (cz + 1) * r2;
        const unsigned lim = (unsigned)(nenc - 1);
        id[0] = min((unsigned)(a0 + b0v + c0v), lim);
        id[1] = min((unsigned)(a0 + b0v + c1v), lim);
        id[2] = min((unsigned)(a0 + b1v + c0v), lim);
        id[3] = min((unsigned)(a0 + b1v + c1v), lim);
        id[4] = min((unsigned)(a1 + b0v + c0v), lim);
        id[5] = min((unsigned)(a1 + b0v + c1v), lim);
        id[6] = min((unsigned)(a1 + b1v + c0v), lim);
        id[7] = min((unsigned)(a1 + b1v + c1v), lim);
    }

    const float w[8] = { w00 * wz0, w00 * wz1, w01 * wz0, w01 * wz1,
                         w10 * wz0, w10 * wz1, w11 * wz0, w11 * wz1 };

    float ax = 0.0f, ay = 0.0f;
    #pragma unroll
    for (int k = 0; k < 8; k++) {
        const float2 e = __half22float2(tab[id[k]]);
        ax = fmaf(w[k], e.x, ax);
        ay = fmaf(w[k], e.y, ay);
    }
    return make_float2(ax, ay);
}

__global__ __launch_bounds__(BT, 1)
void hashenc_kernel(const float* __restrict__ x,
                    const float* __restrict__ emb,
                    float4* __restrict__ out,
                    int npts, int ppb, int nsub)
{
    const int pair = blockIdx.x;
    const int cy   = blockIdx.y;
    const int lA = 2 * pair, lB = 2 * pair + 1;
    const int resA = c_res[lA],  resB = c_res[lB];
    const int neA  = c_nenc[lA], neB  = c_nenc[lB];
    const bool hA = (lA >= 3), hB = (lB >= 3);
    const int tid = threadIdx.x;

    extern __shared__ __half2 smem_[];
    __half2* tabA = smem_;
    __half2* tabB = smem_ + TBL;
    __half2* stg  = smem_ + 2 * TBL;   // NLV x TSTR staging for transpose
    __shared__ int s_last;
    {
        const float2* srcA = reinterpret_cast<const float2*>(emb) + lA * TBL;
        const float2* srcB = reinterpret_cast<const float2*>(emb) + lB * TBL;
        for (int i = tid; i < neA; i += BT) {
            const float2 v = __ldg(srcA + i);
            tabA[i] = __floats2half2_rn(v.x * SC, v.y * SC);
        }
        for (int i = tid; i < neB; i += BT) {
            const float2 v = __ldg(srcB + i);
            tabB[i] = __floats2half2_rn(v.x * SC, v.y * SC);
        }
    }
    __syncthreads();

    __half2* scrA = g_scr + (size_t)lA * npts;
    __half2* scrB = g_scr + (size_t)lB * npts;
    const bool vec_ok = ((npts & 3) == 0);

    for (int st = 0; st < nsub; st++) {
        const int s0 = cy * ppb + st * SUBT;
        if (s0 >= npts) break;
        const int s1 = min(npts, s0 + SUBT);

        // ---- compute this subtile (2 levels), coalesced scratch stores ----
        for (int b = s0 + tid; b < s1; b += BT) {
            const float px = x[3 * b + 0];
            const float py = x[3 * b + 1];
            const float pz = x[3 * b + 2];
            const float2 rA = level_compute(px, py, pz, resA, neA, hA, tabA);
            const float2 rB = level_compute(px, py, pz, resB, neB, hB, tabB);
            scrA[b] = __floats2half2_rn(rA.x, rA.y);
            scrB[b] = __floats2half2_rn(rB.x, rB.y);
        }
        __syncthreads();

        // ---- arrival; 8th arriver transposes the subtile ----
        if (tid == 0) {
            __threadfence();
            const unsigned old = atomicAdd(&g_ctr[(cy << 5) + st], 1u);
            s_last = ((old & 7u) == 7u) ? 1 : 0;
        }
        __syncthreads();

        if (s_last) {
            for (int t0 = s0; t0 < s1; t0 += TPW) {
                const bool fullt = vec_ok && (t0 + TPW <= npts);
                if (fullt) {
                    #pragma unroll
                    for (int idx = tid; idx < NLV * (TPW / 4); idx += BT) {
                        const int l = idx >> 7;       // / 128
                        const int j = idx & 127;
                        const uint4 v = __ldcg(reinterpret_cast<const uint4*>(
                            &g_scr[(size_t)l * npts + t0 + 4 * j]));
                        uint2* dst = reinterpret_cast<uint2*>(&stg[l * TSTR + 4 * j]);
                        dst[0] = make_uint2(v.x, v.y);
                        dst[1] = make_uint2(v.z, v.w);
                    }
                } else {
                    for (int idx = tid; idx < NLV * TPW; idx += BT) {
                        const int l = idx >> 9;
                        const int p = idx & (TPW - 1);
                        stg[l * TSTR + p] = (t0 + p < npts)
                            ? __ldcg(&g_scr[(size_t)l * npts + t0 + p])
                            : __floats2half2_rn(0.f, 0.f);
                    }
                }
                __syncthreads();

                float4* obase = out + (size_t)t0 * 8;
                #pragma unroll
                for (int i = tid; i < TPW * 8; i += BT) {
                    const int p  = i >> 3;
                    const int jp = i & 7;
                    if (fullt || t0 + p < npts) {
                        const float2 e0 = __half22float2(stg[(2 * jp)     * TSTR + p]);
                        const float2 e1 = __half22float2(stg[(2 * jp + 1) * TSTR + p]);
                        __stcs(&obase[i], make_float4(e0.x * SCI, e0.y * SCI,
                                                      e1.x * SCI, e1.y * SCI));
                    }
                }
                __syncthreads();
            }
        }
    }
}

extern "C" void kernel_launch(void* const* d_in, const int* in_sizes, int n_in,
                              void* d_out, int out_size)
{
    const float* x   = (const float*)d_in[0];   // (B, 3) float32
    const float* emb = (const float*)d_in[1];   // (16, 16384, 2) float32
    float4* out      = (float4*)d_out;          // (B, 16, 2) float32

    const int npts = in_sizes[0] / 3;
    int ppb = (npts + NCHUNK - 1) / NCHUNK;
    ppb = (ppb + SUBT - 1) / SUBT * SUBT;       // multiple of SUBT
    const int nsub = ppb / SUBT;                // <= 32 (counter stride)

    const int smem = 2 * TBL * (int)sizeof(__half2)
                   + NLV * TSTR * (int)sizeof(__half2);   // 128KB + 32.1KB

    cudaFuncSetAttribute(hashenc_kernel,
                         cudaFuncAttributeMaxDynamicSharedMemorySize, smem);

    hashenc_kernel<<<dim3(NLV / 2, NCHUNK), BT, smem>>>(x, emb, out,
                                                        npts, ppb, nsub);
}

// round 16
// speedup vs baseline: 1.4951x; 1.4951x over previous
#include <cuda_runtime.h>
#include <cuda_fp16.h>

// Round 16: consolidation. R11 (proven 94.7us: pair-per-block K1 + transpose
// K2) with two verified micro-wins only:
//  - ppb rounded to BT so 36/37 chunks run exact full-width iterations
//  - table fill via float4 (2 entries/LDG), halving fill load instructions
// All overlap schemes (streams x2, in-kernel last-arriver) measured as losses;
// 5-group/192KB-table packing rejected analytically (fill cost > x savings).

#define NLV 16
#define TBL 16384
#define BT  1024           // 32 warps, 1 CTA/SM (128KB: two fp16 tables)
#define NCHUNK 37          // grid (8,37) = 296 blocks = 2 waves
#define SC   8192.0f
#define SCI  (1.0f / 8192.0f)
#define MAXB 1048576

__device__ __half2 g_scr[NLV * MAXB];   // 64 MB, layout (level, point)

__constant__ int c_res[NLV]  = {16, 20, 25, 32, 40, 50, 64, 80,
                                101, 128, 161, 203, 256, 322, 406, 512};
__constant__ int c_nenc[NLV] = {4096, 8000, 15625, 16384, 16384, 16384, 16384, 16384,
                                16384, 16384, 16384, 16384, 16384, 16384, 16384, 16384};

__device__ __forceinline__ float2 level_compute(
    float px, float py, float pz, int res, int nenc, bool hashing,
    const __half2* __restrict__ tab)
{
    const float resf = (float)res;
    const float sx = (px + 1.0f) * resf * 0.5f - 0.5f;
    const float sy = (py + 1.0f) * resf * 0.5f - 0.5f;
    const float sz = (pz + 1.0f) * resf * 0.5f - 0.5f;
    const float flx = floorf(sx), fly = floorf(sy), flz = floorf(sz);
    const float fx = sx - flx, fy = sy - fly, fz = sz - flz;
    const int cx = (int)flx, cy = (int)fly, cz = (int)flz;

    const float wx0 = (cx >= 0)       ? 1.0f - fx : 0.0f;
    const float wx1 = (cx <  res - 1) ? fx        : 0.0f;
    const float wy0 = (cy >= 0)       ? 1.0f - fy : 0.0f;
    const float wy1 = (cy <  res - 1) ? fy        : 0.0f;
    const float wz0 = (cz >= 0)       ? 1.0f - fz : 0.0f;
    const float wz1 = (cz <  res - 1) ? fz        : 0.0f;

    const float w00 = wx0 * wy0, w01 = wx0 * wy1;
    const float w10 = wx1 * wy0, w11 = wx1 * wy1;

    unsigned id[8];
    if (hashing) {
        const unsigned hx0 = (unsigned)cx;
        const unsigned hx1 = (unsigned)(cx + 1);
        const unsigned hy0 = (unsigned)cy       * 2654435761u;
        const unsigned hy1 = (unsigned)(cy + 1) * 2654435761u;
        const unsigned hz0 = (unsigned)cz       * 805459861u;
        const unsigned hz1 = (unsigned)(cz + 1) * 805459861u;
        const unsigned g00 = hx0 ^ hy0, g01 = hx0 ^ hy1;
        const unsigned g10 = hx1 ^ hy0, g11 = hx1 ^ hy1;
        const unsigned m = (unsigned)(nenc - 1);
        id[0] = (g00 ^ hz0) & m;  id[1] = (g00 ^ hz1) & m;
        id[2] = (g01 ^ hz0) & m;  id[3] = (g01 ^ hz1) & m;
        id[4] = (g10 ^ hz0) & m;  id[5] = (g10 ^ hz1) & m;
        id[6] = (g11 ^ hz0) & m;  id[7] = (g11 ^ hz1) & m;
    } else {
        const int r2 = res * res;
        const int a0 = cx,        a1 = cx + 1;
        const int b0v = cy * res, b1v = (cy + 1) * res;
        const int c0v = cz * r2,  c1v = (cz + 1) * r2;
        const unsigned lim = (unsigned)(nenc - 1);
        id[0] = min((unsigned)(a0 + b0v + c0v), lim);
        id[1] = min((unsigned)(a0 + b0v + c1v), lim);
        id[2] = min((unsigned)(a0 + b1v + c0v), lim);
        id[3] = min((unsigned)(a0 + b1v + c1v), lim);
        id[4] = min((unsigned)(a1 + b0v + c0v), lim);
        id[5] = min((unsigned)(a1 + b0v + c1v), lim);
        id[6] = min((unsigned)(a1 + b1v + c0v), lim);
        id[7] = min((unsigned)(a1 + b1v + c1v), lim);
    }

    const float w[8] = { w00 * wz0, w00 * wz1, w01 * wz0, w01 * wz1,
                         w10 * wz0, w10 * wz1, w11 * wz0, w11 * wz1 };

    float ax = 0.0f, ay = 0.0f;
    #pragma unroll
    for (int k = 0; k < 8; k++) {
        const float2 e = __half22float2(tab[id[k]]);   // LDS.32 gather
        ax = fmaf(w[k], e.x, ax);
        ay = fmaf(w[k], e.y, ay);
    }
    return make_float2(ax, ay);
}

// fill one level's table from emb (rows padded to TBL), float4 = 2 entries
__device__ __forceinline__ void fill_table(
    __half2* __restrict__ dst, const float* __restrict__ emb, int level,
    int nenc, int tid)
{
    const float4* src4 = reinterpret_cast<const float4*>(emb) + level * (TBL / 2);
    const int n4 = (nenc + 1) >> 1;   // reading into padding is in-bounds
    for (int i = tid; i < n4; i += BT) {
        const float4 v = __ldg(src4 + i);
        dst[2 * i]     = __floats2half2_rn(v.x * SC, v.y * SC);
        dst[2 * i + 1] = __floats2half2_rn(v.z * SC, v.w * SC);
    }
}

__global__ __launch_bounds__(BT, 1)
void hashenc_kernel(const float* __restrict__ x,
                    const float* __restrict__ emb,
                    int npts, int ppb)
{
    const int pair = blockIdx.x;          // 0..7
    const int lA = 2 * pair, lB = 2 * pair + 1;
    const int resA = c_res[lA],  resB = c_res[lB];
    const int neA  = c_nenc[lA], neB  = c_nenc[lB];
    const bool hA = (lA >= 3), hB = (lB >= 3);
    const int tid = threadIdx.x;

    extern __shared__ __half2 tab[];
    __half2* tabA = tab;
    __half2* tabB = tab + TBL;
    fill_table(tabA, emb, lA, neA, tid);
    fill_table(tabB, emb, lB, neB, tid);
    __syncthreads();

    const int b0 = blockIdx.y * ppb;
    const int b1 = min(npts, b0 + ppb);
    __half2* scrA = g_scr + (size_t)lA * npts;
    __half2* scrB = g_scr + (size_t)lB * npts;

    for (int b = b0 + tid; b < b1; b += BT) {
        const float px = x[3 * b + 0];
        const float py = x[3 * b + 1];
        const float pz = x[3 * b + 2];
        const float2 rA = level_compute(px, py, pz, resA, neA, hA, tabA);
        const float2 rB = level_compute(px, py, pz, resB, neB, hB, tabB);
        scrA[b] = __floats2half2_rn(rA.x, rA.y);
        scrB[b] = __floats2half2_rn(rB.x, rB.y);
    }
}

// (L,B) half2 -> (B,16,2) fp32. Tile 512 pts, 512 thr (4 CTAs/SM).
// Row stride 514 half2: conflict-free in both phases. Identical to R11.
#define TPP 512
#define KT  512
#define TSTR 514

__global__ __launch_bounds__(KT)
void transpose_kernel(float4* __restrict__ out, int npts)
{
    __shared__ __half2 tile[NLV * TSTR];

    const int b0 = blockIdx.x * TPP;
    const int t  = threadIdx.x;
    const bool full = (b0 + TPP <= npts);
    const bool vec  = full && ((npts & 3) == 0);

    if (vec) {
        #pragma unroll
        for (int idx = t; idx < NLV * (TPP / 4); idx += KT) {
            const int l = idx >> 7;
            const int j = idx & 127;
            const uint4 v = __ldcs(reinterpret_cast<const uint4*>(
                &g_scr[(size_t)l * npts + b0 + 4 * j]));
            uint2* dst = reinterpret_cast<uint2*>(&tile[l * TSTR + 4 * j]);
            dst[0] = make_uint2(v.x, v.y);
            dst[1] = make_uint2(v.z, v.w);
        }
    } else {
        for (int idx = t; idx < NLV * TPP; idx += KT) {
            const int l = idx >> 9;
            const int p = idx & (TPP - 1);
            tile[l * TSTR + p] = (b0 + p < npts)
                ? g_scr[(size_t)l * npts + b0 + p]
                : __floats2half2_rn(0.f, 0.f);
        }
    }
    __syncthreads();

    float4* obase = out + (size_t)b0 * 8;
    #pragma unroll
    for (int i = t; i < TPP * 8; i += KT) {
        const int p  = i >> 3;
        const int jp = i & 7;
        if (full || b0 + p < npts) {
            const float2 e0 = __half22float2(tile[(2 * jp)     * TSTR + p]);
            const float2 e1 = __half22float2(tile[(2 * jp + 1) * TSTR + p]);
            __stcs(&obase[i],
                   make_float4(e0.x * SCI, e0.y * SCI, e1.x * SCI, e1.y * SCI));
        }
    }
}

extern "C" void kernel_launch(void* const* d_in, const int* in_sizes, int n_in,
                              void* d_out, int out_size)
{
    const float* x   = (const float*)d_in[0];   // (B, 3) float32
    const float* emb = (const float*)d_in[1];   // (16, 16384, 2) float32
    float4* out      = (float4*)d_out;          // (B, 16, 2) float32

    const int npts = in_sizes[0] / 3;
    // ppb: ceil over 37 chunks, rounded up to BT so full chunks have no
    // partial-tail iteration (36 full + 1 short chunk)
    int ppb = (npts + NCHUNK - 1) / NCHUNK;
    ppb = (ppb + BT - 1) / BT * BT;
    const int smem = 2 * TBL * (int)sizeof(__half2); // 128 KB

    cudaFuncSetAttribute(hashenc_kernel,
                         cudaFuncAttributeMaxDynamicSharedMemorySize, smem);

    hashenc_kernel<<<dim3(NLV / 2, NCHUNK), BT, smem>>>(x, emb, npts, ppb);
    transpose_kernel<<<(npts + TPP - 1) / TPP, KT>>>(out, npts);
}

// round 17
// speedup vs baseline: 2.3306x; 1.5589x over previous
#include <cuda_runtime.h>
#include <cuda_fp16.h>

// Round 17: byte-identical revert to R11 (best: 94.7us) as a controlled
// re-measurement. R16 (+ppb rounding, +float4 fill, returning level_compute)
// measured 152us, but its K2 — code-identical to R11's — ran 28% slower,
// implicating DVFS/machine state; K1's extra slowdown beyond clock is
// confounded with the refactor. Reverting isolates the variables.

#define NLV 16
#define TBL 16384
#define BT  1024           // 32 warps, 1 CTA/SM
#define NCHUNK 37
#define MAXB 1048576
#define SC   8192.0f
#define SCI  (1.0f / 8192.0f)

__device__ __half2 g_scr[NLV * MAXB];   // 64 MB, layout (level, point)

__constant__ int c_res[NLV]  = {16, 20, 25, 32, 40, 50, 64, 80,
                                101, 128, 161, 203, 256, 322, 406, 512};
__constant__ int c_nenc[NLV] = {4096, 8000, 15625, 16384, 16384, 16384, 16384, 16384,
                                16384, 16384, 16384, 16384, 16384, 16384, 16384, 16384};

__device__ __forceinline__ void level_compute(
    float px, float py, float pz, int res, int nenc, bool hashing,
    const __half2* __restrict__ tab, __half2* __restrict__ scr, int b)
{
    const float resf = (float)res;
    const float sx = (px + 1.0f) * resf * 0.5f - 0.5f;
    const float sy = (py + 1.0f) * resf * 0.5f - 0.5f;
    const float sz = (pz + 1.0f) * resf * 0.5f - 0.5f;
    const float flx = floorf(sx), fly = floorf(sy), flz = floorf(sz);
    const float fx = sx - flx, fy = sy - fly, fz = sz - flz;
    const int cx = (int)flx, cy = (int)fly, cz = (int)flz;

    const float wx0 = (cx >= 0)       ? 1.0f - fx : 0.0f;
    const float wx1 = (cx <  res - 1) ? fx        : 0.0f;
    const float wy0 = (cy >= 0)       ? 1.0f - fy : 0.0f;
    const float wy1 = (cy <  res - 1) ? fy        : 0.0f;
    const float wz0 = (cz >= 0)       ? 1.0f - fz : 0.0f;
    const float wz1 = (cz <  res - 1) ? fz        : 0.0f;

    const float w00 = wx0 * wy0, w01 = wx0 * wy1;
    const float w10 = wx1 * wy0, w11 = wx1 * wy1;

    unsigned id[8];
    if (hashing) {
        const unsigned hx0 = (unsigned)cx;
        const unsigned hx1 = (unsigned)(cx + 1);
        const unsigned hy0 = (unsigned)cy       * 2654435761u;
        const unsigned hy1 = (unsigned)(cy + 1) * 2654435761u;
        const unsigned hz0 = (unsigned)cz       * 805459861u;
        const unsigned hz1 = (unsigned)(cz + 1) * 805459861u;
        const unsigned g00 = hx0 ^ hy0, g01 = hx0 ^ hy1;
        const unsigned g10 = hx1 ^ hy0, g11 = hx1 ^ hy1;
        const unsigned m = (unsigned)(nenc - 1);
        id[0] = (g00 ^ hz0) & m;  id[1] = (g00 ^ hz1) & m;
        id[2] = (g01 ^ hz0) & m;  id[3] = (g01 ^ hz1) & m;
        id[4] = (g10 ^ hz0) & m;  id[5] = (g10 ^ hz1) & m;
        id[6] = (g11 ^ hz0) & m;  id[7] = (g11 ^ hz1) & m;
    } else {
        const int r2 = res * res;
        const int a0 = cx,        a1 = cx + 1;
        const int b0v = cy * res, b1v = (cy + 1) * res;
        const int c0v = cz * r2,  c1v = (cz + 1) * r2;
        const unsigned lim = (unsigned)(nenc - 1);
        id[0] = min((unsigned)(a0 + b0v + c0v), lim);
        id[1] = min((unsigned)(a0 + b0v + c1v), lim);
        id[2] = min((unsigned)(a0 + b1v + c0v), lim);
        id[3] = min((unsigned)(a0 + b1v + c1v), lim);
        id[4] = min((unsigned)(a1 + b0v + c0v), lim);
        id[5] = min((unsigned)(a1 + b0v + c1v), lim);
        id[6] = min((unsigned)(a1 + b1v + c0v), lim);
        id[7] = min((unsigned)(a1 + b1v + c1v), lim);
    }

    const float w[8] = { w00 * wz0, w00 * wz1, w01 * wz0, w01 * wz1,
                         w10 * wz0, w10 * wz1, w11 * wz0, w11 * wz1 };

    float ax = 0.0f, ay = 0.0f;
    #pragma unroll
    for (int k = 0; k < 8; k++) {
        const float2 e = __half22float2(tab[id[k]]);   // LDS.32 gather
        ax = fmaf(w[k], e.x, ax);
        ay = fmaf(w[k], e.y, ay);
    }

    scr[b] = __floats2half2_rn(ax, ay);   // table carries the x8192 scale
}

__global__ __launch_bounds__(BT, 1)
void hashenc_kernel(const float* __restrict__ x,
                    const float* __restrict__ emb,
                    int npts, int ppb)
{
    const int pair = blockIdx.x;          // 0..7
    const int lA = 2 * pair, lB = 2 * pair + 1;
    const int resA = c_res[lA],  resB = c_res[lB];
    const int neA  = c_nenc[lA], neB  = c_nenc[lB];
    const bool hA = (lA >= 3), hB = (lB >= 3);

    extern __shared__ __half2 tab[];
    __half2* tabA = tab;
    __half2* tabB = tab + TBL;
    {
        const float2* srcA = reinterpret_cast<const float2*>(emb) + lA * TBL;
        const float2* srcB = reinterpret_cast<const float2*>(emb) + lB * TBL;
        for (int i = threadIdx.x; i < neA; i += BT) {
            const float2 v = __ldg(srcA + i);
            tabA[i] = __floats2half2_rn(v.x * SC, v.y * SC);
        }
        for (int i = threadIdx.x; i < neB; i += BT) {
            const float2 v = __ldg(srcB + i);
            tabB[i] = __floats2half2_rn(v.x * SC, v.y * SC);
        }
    }
    __syncthreads();

    const int b0 = blockIdx.y * ppb;
    const int b1 = min(npts, b0 + ppb);
    __half2* scrA = g_scr + (size_t)lA * npts;
    __half2* scrB = g_scr + (size_t)lB * npts;

    for (int b = b0 + (int)threadIdx.x; b < b1; b += BT) {
        const float px = x[3 * b + 0];
        const float py = x[3 * b + 1];
        const float pz = x[3 * b + 2];
        level_compute(px, py, pz, resA, neA, hA, tabA, scrA, b);
        level_compute(px, py, pz, resB, neB, hB, tabB, scrB, b);
    }
}

// (L,B) half2 -> (B,16,2) fp32. Tile 512 points, 512 threads (4 CTAs/SM).
// Smem row stride 514 half2: conflict-free in both phases.
#define TPP 512
#define KT  512
#define TSTR 514

__global__ __launch_bounds__(KT)
void transpose_kernel(float4* __restrict__ out, int npts)
{
    __shared__ __half2 tile[NLV * TSTR];

    const int b0 = blockIdx.x * TPP;
    const int t  = threadIdx.x;
    const bool full = (b0 + TPP <= npts);

    if (full) {
        #pragma unroll
        for (int idx = t; idx < NLV * (TPP / 4); idx += KT) {
            const int l = idx >> 7;
            const int j = idx & 127;
            const uint4 v = __ldcs(reinterpret_cast<const uint4*>(
                &g_scr[(size_t)l * npts + b0 + 4 * j]));
            uint2* dst = reinterpret_cast<uint2*>(&tile[l * TSTR + 4 * j]);
            dst[0] = make_uint2(v.x, v.y);
            dst[1] = make_uint2(v.z, v.w);
        }
    } else {
        for (int idx = t; idx < NLV * TPP; idx += KT) {
            const int l = idx >> 9;
            const int p = idx & (TPP - 1);
            tile[l * TSTR + p] = (b0 + p < npts)
                ? g_scr[(size_t)l * npts + b0 + p]
                : __floats2half2_rn(0.f, 0.f);
        }
    }
    __syncthreads();

    float4* obase = out + (size_t)b0 * 8;
    #pragma unroll
    for (int i = t; i < TPP * 8; i += KT) {
        const int p  = i >> 3;
        const int jp = i & 7;
        if (full || b0 + p < npts) {
            const float2 e0 = __half22float2(tile[(2 * jp)     * TSTR + p]);
            const float2 e1 = __half22float2(tile[(2 * jp + 1) * TSTR + p]);
            __stcs(&obase[i],
                   make_float4(e0.x * SCI, e0.y * SCI, e1.x * SCI, e1.y * SCI));
        }
    }
}

extern "C" void kernel_launch(void* const* d_in, const int* in_sizes, int n_in,
                              void* d_out, int out_size)
{
    const float* x   = (const float*)d_in[0];   // (B, 3) float32
    const float* emb = (const float*)d_in[1];   // (16, 16384, 2) float32
    float4* out      = (float4*)d_out;          // (B, 16, 2) float32

    const int npts = in_sizes[0] / 3;
    const int ppb  = (npts + NCHUNK - 1) / NCHUNK;
    const int smem = 2 * TBL * (int)sizeof(__half2); // 128 KB (two tables)

    cudaFuncSetAttribute(hashenc_kernel,
                         cudaFuncAttributeMaxDynamicSharedMemorySize, smem);

    hashenc_kernel<<<dim3(NLV / 2, NCHUNK), BT, smem>>>(x, emb, npts, ppb);
    transpose_kernel<<<(npts + TPP - 1) / TPP, KT>>>(out, npts);
}